// round 2
// baseline (speedup 1.0000x reference)
#include <cuda_runtime.h>

// PrototypeLoss: loss = 0.5*CE(logits, labels) + 0.5*proto_loss(normalize(emb), labels)
// N=262144, D=128, C=64. labels are int32 (JAX x64 disabled downcasts int64->int32).

#define NPART 16
#define C 64
#define D 128

__device__ float g_part[NPART * C * D];  // partitioned class sums of z
__device__ float g_cnt[C];
__device__ float g_sq[C];
__device__ float g_ce;

__global__ void zero_kernel() {
    int tid = blockIdx.x * blockDim.x + threadIdx.x;
    int stride = gridDim.x * blockDim.x;
    for (int i = tid; i < NPART * C * D; i += stride) g_part[i] = 0.0f;
    if (tid < C) { g_cnt[tid] = 0.0f; g_sq[tid] = 0.0f; }
    if (tid == 0) g_ce = 0.0f;
}

__global__ void __launch_bounds__(256) main_kernel(
    const float* __restrict__ emb,
    const float* __restrict__ logits,
    const int* __restrict__ labels,
    int N)
{
    const int lane = threadIdx.x & 31;
    const int wid = threadIdx.x >> 5;
    const int warpsPerBlock = blockDim.x >> 5;
    const int warpGlobal = blockIdx.x * warpsPerBlock + wid;
    const int nWarps = gridDim.x * warpsPerBlock;

    float* part = g_part + (blockIdx.x & (NPART - 1)) * (C * D);

    float ce = 0.0f;

    for (int r = warpGlobal; r < N; r += nWarps) {
        // ---- load emb row: lane holds 4 contiguous floats (coalesced 512B) ----
        float4 v = reinterpret_cast<const float4*>(emb)[(size_t)r * 32 + lane];
        float ss = v.x * v.x + v.y * v.y + v.z * v.z + v.w * v.w;
        #pragma unroll
        for (int o = 16; o; o >>= 1) ss += __shfl_xor_sync(0xffffffffu, ss, o);

        float nrm = sqrtf(ss);
        float s = 1.0f / fmaxf(nrm, 1e-12f);

        int c = labels[r] & (C - 1);  // uniform broadcast load; mask is semantically free

        // ---- scatter z into partitioned class sums (vec4 global red) ----
        float* dst = part + c * D + lane * 4;
        asm volatile("red.global.add.v4.f32 [%0], {%1,%2,%3,%4};"
                     :: "l"(dst), "f"(v.x * s), "f"(v.y * s), "f"(v.z * s), "f"(v.w * s)
                     : "memory");

        if (lane == 0) {
            atomicAdd(&g_cnt[c], 1.0f);
            atomicAdd(&g_sq[c], ss * s * s);  // sum ||z||^2
        }

        // ---- cross-entropy: 64 logits, 2 per lane ----
        const float* lg = logits + (size_t)r * 64;
        float x0 = lg[lane];
        float x1 = lg[lane + 32];
        float m = fmaxf(x0, x1);
        #pragma unroll
        for (int o = 16; o; o >>= 1) m = fmaxf(m, __shfl_xor_sync(0xffffffffu, m, o));
        float e = expf(x0 - m) + expf(x1 - m);
        #pragma unroll
        for (int o = 16; o; o >>= 1) e += __shfl_xor_sync(0xffffffffu, e, o);
        float lse = m + logf(e);
        float src = (c < 32) ? x0 : x1;   // c uniform across warp
        float tv = __shfl_sync(0xffffffffu, src, c & 31);
        ce += lse - tv;
    }

    // ce is lane-uniform (all terms came from warp-wide allreduces)
    __shared__ float sce[32];
    if (lane == 0) sce[wid] = ce;
    __syncthreads();
    if (threadIdx.x == 0) {
        float t = 0.0f;
        for (int i = 0; i < warpsPerBlock; i++) t += sce[i];
        atomicAdd(&g_ce, t);
    }
}

__global__ void finalize_kernel(float* __restrict__ out, int N) {
    const int lane = threadIdx.x & 31;
    const int wid = threadIdx.x >> 5;  // 8 warps, warp handles classes wid, wid+8, ...
    __shared__ float s_proto[8];
    __shared__ float s_nv[8];

    float proto = 0.0f, nv = 0.0f;

    for (int c = wid; c < C; c += 8) {
        float musq = 0.0f;  // sum_d (sum_i z_id)^2
        #pragma unroll
        for (int k = 0; k < 4; k++) {
            int d = lane + 32 * k;
            float sum = 0.0f;
            #pragma unroll
            for (int p = 0; p < NPART; p++) sum += g_part[p * (C * D) + c * D + d];
            musq += sum * sum;
        }
        #pragma unroll
        for (int o = 16; o; o >>= 1) musq += __shfl_xor_sync(0xffffffffu, musq, o);

        if (lane == 0) {
            float n = g_cnt[c];
            float sn = fmaxf(n, 1.0f);
            float mu2 = musq / (sn * sn);       // ||mu||^2
            float ssd = g_sq[c] - n * mu2;
            float per = ssd / sn;
            if (n > 1.0f) { proto += per; nv += 1.0f; }
        }
    }

    if (lane == 0) { s_proto[wid] = proto; s_nv[wid] = nv; }
    __syncthreads();
    if (threadIdx.x == 0) {
        float ps = 0.0f, ns = 0.0f;
        for (int i = 0; i < 8; i++) { ps += s_proto[i]; ns += s_nv[i]; }
        float proto_loss = ps / fmaxf(ns, 1.0f);
        float ce = g_ce / (float)N;
        out[0] = 0.5f * ce + 0.5f * proto_loss;
    }
}

extern "C" void kernel_launch(void* const* d_in, const int* in_sizes, int n_in,
                              void* d_out, int out_size) {
    const float* emb = (const float*)d_in[0];
    const float* logits = (const float*)d_in[1];
    const int* labels = (const int*)d_in[2];
    int N = in_sizes[0] / D;

    zero_kernel<<<64, 256>>>();
    main_kernel<<<148 * 8, 256>>>(emb, logits, labels, N);
    finalize_kernel<<<1, 256>>>((float*)d_out, N);
}

// round 4
// speedup vs baseline: 1.6284x; 1.6284x over previous
#include <cuda_runtime.h>

// PrototypeLoss: loss = 0.5*CE(logits, labels) + 0.5*proto_loss(normalize(emb), labels)
// N=262144, D=128, C=64. labels int32.
// Segment-sum strategy: block-local register accumulation (warp owns 4 classes),
// single RED flush at end -> 14x less L2 atomic traffic than per-row RED.

#define C 64
#define D 128
#define NPART 16
#define NWARPS 16
#define ROWS_PER_WARP 4
#define BATCH (NWARPS * ROWS_PER_WARP)   // 64 rows staged per batch
#define GRID 296

__device__ float g_part[NPART * C * D];
__device__ float g_cnt[C];
__device__ float g_sq[C];
__device__ float g_ce;

__global__ void zero_kernel() {
    int tid = blockIdx.x * blockDim.x + threadIdx.x;
    int stride = gridDim.x * blockDim.x;
    for (int i = tid; i < NPART * C * D; i += stride) g_part[i] = 0.0f;
    if (tid < C) { g_cnt[tid] = 0.0f; g_sq[tid] = 0.0f; }
    if (tid == 0) g_ce = 0.0f;
}

__device__ __forceinline__ void red_v4(float* dst, float4 v) {
    asm volatile("red.global.add.v4.f32 [%0], {%1,%2,%3,%4};"
                 :: "l"(dst), "f"(v.x), "f"(v.y), "f"(v.z), "f"(v.w) : "memory");
}

__global__ void __launch_bounds__(512, 2) main_kernel(
    const float* __restrict__ emb,
    const float* __restrict__ logits,
    const int* __restrict__ labels,
    int N)
{
    __shared__ float s_z[BATCH][D];     // 32 KB staged normalized rows
    __shared__ int   s_lab[BATCH];
    __shared__ float s_cnt[C];
    __shared__ float s_sq[C];
    __shared__ float s_ce[NWARPS];

    const int tid  = threadIdx.x;
    const int lane = tid & 31;
    const int wid  = tid >> 5;
    const int wClass = wid * 4;         // this warp owns classes [wClass, wClass+4)

    if (tid < C) { s_cnt[tid] = 0.0f; s_sq[tid] = 0.0f; }

    float4 acc0 = {0,0,0,0}, acc1 = {0,0,0,0}, acc2 = {0,0,0,0}, acc3 = {0,0,0,0};
    float ce = 0.0f;

    const int nBatches = N / BATCH;     // 4096 for N=262144

    for (int b = blockIdx.x; b < nBatches; b += gridDim.x) {
        __syncthreads();   // staging buffer reusable (also orders s_cnt init)

        // ---------- Phase A: normalize + stage + CE ----------
        #pragma unroll
        for (int k = 0; k < ROWS_PER_WARP; k++) {
            int j = wid * ROWS_PER_WARP + k;     // row slot in batch
            int r = b * BATCH + j;

            float4 v = reinterpret_cast<const float4*>(emb)[(size_t)r * 32 + lane];
            float ss = v.x * v.x + v.y * v.y + v.z * v.z + v.w * v.w;
            #pragma unroll
            for (int o = 16; o; o >>= 1) ss += __shfl_xor_sync(0xffffffffu, ss, o);

            float s = 1.0f / fmaxf(sqrtf(ss), 1e-12f);
            int c = labels[r] & (C - 1);

            float4 z = {v.x * s, v.y * s, v.z * s, v.w * s};
            *reinterpret_cast<float4*>(&s_z[j][lane * 4]) = z;

            if (lane == 0) {
                s_lab[j] = c;
                atomicAdd(&s_cnt[c], 1.0f);
                atomicAdd(&s_sq[c], ss * s * s);
            }

            // cross-entropy: 64 logits, 2 per lane
            const float* lg = logits + (size_t)r * 64;
            float x0 = lg[lane];
            float x1 = lg[lane + 32];
            float m = fmaxf(x0, x1);
            #pragma unroll
            for (int o = 16; o; o >>= 1) m = fmaxf(m, __shfl_xor_sync(0xffffffffu, m, o));
            float e = expf(x0 - m) + expf(x1 - m);
            #pragma unroll
            for (int o = 16; o; o >>= 1) e += __shfl_xor_sync(0xffffffffu, e, o);
            float lse = m + logf(e);
            float src = (c < 32) ? x0 : x1;     // c uniform across warp
            float tv = __shfl_sync(0xffffffffu, src, c & 31);
            ce += lse - tv;
        }

        __syncthreads();

        // ---------- Phase B: each warp accumulates its 4 owned classes ----------
        for (int j = 0; j < BATCH; j++) {
            int rel = s_lab[j] - wClass;        // broadcast LDS
            if ((unsigned)rel < 4u) {
                float4 z = *reinterpret_cast<const float4*>(&s_z[j][lane * 4]);
                if (rel == 0) { acc0.x += z.x; acc0.y += z.y; acc0.z += z.z; acc0.w += z.w; }
                if (rel == 1) { acc1.x += z.x; acc1.y += z.y; acc1.z += z.z; acc1.w += z.w; }
                if (rel == 2) { acc2.x += z.x; acc2.y += z.y; acc2.z += z.z; acc2.w += z.w; }
                if (rel == 3) { acc3.x += z.x; acc3.y += z.y; acc3.z += z.z; acc3.w += z.w; }
            }
        }
    }

    // ---------- Flush class sums (one vec4 RED per class per lane) ----------
    float* part = g_part + (blockIdx.x & (NPART - 1)) * (C * D);
    red_v4(part + (wClass + 0) * D + lane * 4, acc0);
    red_v4(part + (wClass + 1) * D + lane * 4, acc1);
    red_v4(part + (wClass + 2) * D + lane * 4, acc2);
    red_v4(part + (wClass + 3) * D + lane * 4, acc3);

    // ---------- Flush CE ----------
    if (lane == 0) s_ce[wid] = ce;   // ce is lane-uniform
    __syncthreads();
    if (tid == 0) {
        float t = 0.0f;
        #pragma unroll
        for (int i = 0; i < NWARPS; i++) t += s_ce[i];
        atomicAdd(&g_ce, t);
    }

    // ---------- Flush counts / sq ----------
    if (tid < C) {
        atomicAdd(&g_cnt[tid], s_cnt[tid]);
        atomicAdd(&g_sq[tid], s_sq[tid]);
    }
}

__global__ void finalize_kernel(float* __restrict__ out, int N) {
    const int lane = threadIdx.x & 31;
    const int wid = threadIdx.x >> 5;  // 8 warps, warp handles classes wid, wid+8, ...
    __shared__ float s_proto[8];
    __shared__ float s_nv[8];

    float proto = 0.0f, nv = 0.0f;

    for (int c = wid; c < C; c += 8) {
        float musq = 0.0f;
        #pragma unroll
        for (int k = 0; k < 4; k++) {
            int d = lane + 32 * k;
            float sum = 0.0f;
            #pragma unroll
            for (int p = 0; p < NPART; p++) sum += g_part[p * (C * D) + c * D + d];
            musq += sum * sum;
        }
        #pragma unroll
        for (int o = 16; o; o >>= 1) musq += __shfl_xor_sync(0xffffffffu, musq, o);

        if (lane == 0) {
            float n = g_cnt[c];
            float sn = fmaxf(n, 1.0f);
            float mu2 = musq / (sn * sn);
            float ssd = g_sq[c] - n * mu2;
            float per = ssd / sn;
            if (n > 1.0f) { proto += per; nv += 1.0f; }
        }
    }

    if (lane == 0) { s_proto[wid] = proto; s_nv[wid] = nv; }
    __syncthreads();
    if (threadIdx.x == 0) {
        float ps = 0.0f, ns = 0.0f;
        for (int i = 0; i < 8; i++) { ps += s_proto[i]; ns += s_nv[i]; }
        float proto_loss = ps / fmaxf(ns, 1.0f);
        float ce = g_ce / (float)N;
        out[0] = 0.5f * ce + 0.5f * proto_loss;
    }
}

extern "C" void kernel_launch(void* const* d_in, const int* in_sizes, int n_in,
                              void* d_out, int out_size) {
    const float* emb = (const float*)d_in[0];
    const float* logits = (const float*)d_in[1];
    const int* labels = (const int*)d_in[2];
    int N = in_sizes[0] / D;

    zero_kernel<<<64, 256>>>();
    main_kernel<<<GRID, 512>>>(emb, logits, labels, N);
    finalize_kernel<<<1, 256>>>((float*)d_out, N);
}

// round 6
// speedup vs baseline: 2.4578x; 1.5093x over previous
#include <cuda_runtime.h>

// PrototypeLoss: loss = 0.5*CE(logits, labels) + 0.5*proto_loss(normalize(emb), labels)
// N=262144, D=128, C=64. labels int32.
// Block-local register segment-sum with per-batch hitmask (no 64-row scan),
// single RED flush per block; finalize fused via last-block-done.

#define C 64
#define D 128
#define NPART 16
#define NWARPS 16
#define RPW 4
#define BATCH (NWARPS * RPW)   // 64 rows per staged batch
#define GRID 296

#define PART_ELEMS (NPART * C * D)
#define CNT_OFF  PART_ELEMS
#define SQ_OFF   (CNT_OFF + C)
#define CE_OFF   (SQ_OFF + C)
#define DONE_OFF (CE_OFF + 1)
#define BUF_ELEMS (DONE_OFF + 1)

__device__ float g_buf[BUF_ELEMS];   // [part | cnt | sq | ce | done] zeroed by one memset

__device__ __forceinline__ void red_v4(float* dst, float4 v) {
    asm volatile("red.global.add.v4.f32 [%0], {%1,%2,%3,%4};"
                 :: "l"(dst), "f"(v.x), "f"(v.y), "f"(v.z), "f"(v.w) : "memory");
}

__global__ void __launch_bounds__(512, 2) main_kernel(
    const float* __restrict__ emb,
    const float* __restrict__ logits,
    const int* __restrict__ labels,
    int N, float* __restrict__ out)
{
    __shared__ float s_z[BATCH][D];               // 32 KB staged normalized rows
    __shared__ unsigned long long s_hit[C];       // per-class row bitmask for this batch
    __shared__ float s_cnt[C];
    __shared__ float s_sq[C];
    __shared__ float s_red[NWARPS];
    __shared__ float s_red2[NWARPS];
    __shared__ int s_last;

    const int tid  = threadIdx.x;
    const int lane = tid & 31;
    const int wid  = tid >> 5;
    const int wClass = wid * 4;                   // warp owns classes [wClass, wClass+4)

    if (tid < C) { s_cnt[tid] = 0.0f; s_sq[tid] = 0.0f; s_hit[tid] = 0ull; }

    float4 acc[4];
    #pragma unroll
    for (int i = 0; i < 4; i++) acc[i] = make_float4(0.f, 0.f, 0.f, 0.f);
    float ce = 0.0f;

    const int nBatches = N / BATCH;               // 4096

    for (int b = blockIdx.x; b < nBatches; b += gridDim.x) {
        __syncthreads();   // prev Phase B done; s_hit reset visible

        // ---------- Phase A: normalize + stage + hitmask + CE ----------
        #pragma unroll
        for (int k = 0; k < RPW; k++) {
            int j = wid * RPW + k;
            int r = b * BATCH + j;

            float4 v = reinterpret_cast<const float4*>(emb)[(size_t)r * 32 + lane];
            float ss = v.x * v.x + v.y * v.y + v.z * v.z + v.w * v.w;
            #pragma unroll
            for (int o = 16; o; o >>= 1) ss += __shfl_xor_sync(0xffffffffu, ss, o);

            float s = rsqrtf(fmaxf(ss, 1e-24f));
            int c = labels[r] & (C - 1);

            float4 z = {v.x * s, v.y * s, v.z * s, v.w * s};
            *reinterpret_cast<float4*>(&s_z[j][lane * 4]) = z;

            if (lane == 0) {
                atomicOr(&s_hit[c], 1ull << j);
                atomicAdd(&s_cnt[c], 1.0f);
                atomicAdd(&s_sq[c], ss * s * s);  // ||z||^2
            }

            // cross-entropy: coalesced float2 (logits 2*lane, 2*lane+1), no max-sub
            float2 x = reinterpret_cast<const float2*>(logits + (size_t)r * 64)[lane];
            float e = __expf(x.x) + __expf(x.y);
            #pragma unroll
            for (int o = 16; o; o >>= 1) e += __shfl_xor_sync(0xffffffffu, e, o);
            float lse = logf(e);
            float src = (c & 1) ? x.y : x.x;      // c uniform across warp
            float tv = __shfl_sync(0xffffffffu, src, c >> 1);
            ce += lse - tv;
        }

        __syncthreads();

        // ---------- Phase B: iterate only hit rows via bitmask ----------
        #pragma unroll
        for (int cc = 0; cc < 4; cc++) {
            unsigned long long m = s_hit[wClass + cc];   // broadcast LDS.64
            while (m) {
                int j = __ffsll((long long)m) - 1;
                m &= m - 1;
                float4 z = *reinterpret_cast<const float4*>(&s_z[j][lane * 4]);
                acc[cc].x += z.x; acc[cc].y += z.y; acc[cc].z += z.z; acc[cc].w += z.w;
            }
            s_hit[wClass + cc] = 0ull;            // reset own class (no race: warp owns it)
        }
    }

    // ---------- Flush class sums (one vec4 RED per class per lane) ----------
    float* part = g_buf + (blockIdx.x & (NPART - 1)) * (C * D);
    #pragma unroll
    for (int cc = 0; cc < 4; cc++)
        red_v4(part + (wClass + cc) * D + lane * 4, acc[cc]);

    // ---------- Flush CE + counts/sq ----------
    if (lane == 0) s_red[wid] = ce;               // ce lane-uniform
    __syncthreads();
    if (tid == 0) {
        float t = 0.0f;
        #pragma unroll
        for (int i = 0; i < NWARPS; i++) t += s_red[i];
        atomicAdd(&g_buf[CE_OFF], t);
    }
    if (tid < C) {
        atomicAdd(&g_buf[CNT_OFF + tid], s_cnt[tid]);
        atomicAdd(&g_buf[SQ_OFF + tid], s_sq[tid]);
    }

    // ---------- Last-block finalize ----------
    __threadfence();
    __syncthreads();
    if (tid == 0) {
        unsigned prev = atomicAdd((unsigned int*)&g_buf[DONE_OFF], 1u);
        s_last = (prev == gridDim.x - 1) ? 1 : 0;
    }
    __syncthreads();
    if (s_last) {
        __threadfence();
        float proto = 0.0f, nv = 0.0f;
        for (int c = wid; c < C; c += NWARPS) {
            float musq = 0.0f;
            #pragma unroll
            for (int k = 0; k < 4; k++) {
                int d = lane + 32 * k;
                float sum = 0.0f;
                #pragma unroll
                for (int p = 0; p < NPART; p++) sum += g_buf[p * (C * D) + c * D + d];
                musq += sum * sum;
            }
            #pragma unroll
            for (int o = 16; o; o >>= 1) musq += __shfl_xor_sync(0xffffffffu, musq, o);
            if (lane == 0) {
                float n  = g_buf[CNT_OFF + c];
                float sn = fmaxf(n, 1.0f);
                float mu2 = musq / (sn * sn);
                float ssd = g_buf[SQ_OFF + c] - n * mu2;
                if (n > 1.0f) { proto += ssd / sn; nv += 1.0f; }
            }
        }
        if (lane == 0) { s_red[wid] = proto; s_red2[wid] = nv; }
        __syncthreads();
        if (tid == 0) {
            float ps = 0.0f, ns = 0.0f;
            #pragma unroll
            for (int i = 0; i < NWARPS; i++) { ps += s_red[i]; ns += s_red2[i]; }
            float proto_loss = ps / fmaxf(ns, 1.0f);
            float cem = g_buf[CE_OFF] / (float)N;
            out[0] = 0.5f * cem + 0.5f * proto_loss;
        }
    }
}

extern "C" void kernel_launch(void* const* d_in, const int* in_sizes, int n_in,
                              void* d_out, int out_size) {
    const float* emb = (const float*)d_in[0];
    const float* logits = (const float*)d_in[1];
    const int* labels = (const int*)d_in[2];
    int N = in_sizes[0] / D;

    void* bufAddr = nullptr;
    cudaGetSymbolAddress(&bufAddr, g_buf);
    cudaMemsetAsync(bufAddr, 0, BUF_ELEMS * sizeof(float));

    main_kernel<<<GRID, 512>>>(emb, logits, labels, N, (float*)d_out);
}

// round 8
// speedup vs baseline: 3.4955x; 1.4222x over previous
#include <cuda_runtime.h>

// PrototypeLoss: loss = 0.5*CE(logits, labels) + 0.5*proto_loss(normalize(emb), labels)
// N=262144, D=128, C=64. labels int32.
// Phase A: 8-lane groups own one row each -> 3-shuffle reductions (vs 5) done once
// for 4 rows concurrently. Hitmask Phase B, popcount counts, single RED flush,
// fused last-block finalize.

#define C 64
#define D 128
#define NPART 16
#define NWARPS 16
#define RPW 4
#define BATCH (NWARPS * RPW)   // 64 rows per staged batch
#define GRID 296
#define FULL 0xffffffffu

#define PART_ELEMS (NPART * C * D)
#define CNT_OFF  PART_ELEMS
#define CE_OFF   (CNT_OFF + C)
#define DONE_OFF (CE_OFF + 1)
#define BUF_ELEMS (DONE_OFF + 1)

__device__ float g_buf[BUF_ELEMS];   // [part | cnt | ce | done] zeroed by one memset

__device__ __forceinline__ void red_v4(float* dst, float4 v) {
    asm volatile("red.global.add.v4.f32 [%0], {%1,%2,%3,%4};"
                 :: "l"(dst), "f"(v.x), "f"(v.y), "f"(v.z), "f"(v.w) : "memory");
}

__global__ void __launch_bounds__(512, 2) main_kernel(
    const float* __restrict__ emb,
    const float* __restrict__ logits,
    const int* __restrict__ labels,
    int N, float* __restrict__ out)
{
    __shared__ float s_z[BATCH][D];               // 32 KB staged normalized rows
    __shared__ unsigned long long s_hit[C];       // per-class row bitmask
    __shared__ float s_red[NWARPS];
    __shared__ float s_red2[NWARPS];
    __shared__ int s_last;

    const int tid  = threadIdx.x;
    const int lane = tid & 31;
    const int wid  = tid >> 5;
    const int wClass = wid * 4;                   // warp owns classes [wClass, wClass+4)
    const int k = lane >> 3;                      // which of the warp's 4 rows
    const int q = lane & 7;                       // eighth within the row

    if (tid < C) s_hit[tid] = 0ull;

    float4 acc[4];
    #pragma unroll
    for (int i = 0; i < 4; i++) acc[i] = make_float4(0.f, 0.f, 0.f, 0.f);
    int cnt[4] = {0, 0, 0, 0};
    float ce = 0.0f;                              // accumulated by all 8 group lanes (/8 later)

    const int nBatches = N / BATCH;               // 4096

    for (int b = blockIdx.x; b < nBatches; b += gridDim.x) {
        __syncthreads();   // prev Phase B done; s_hit reset visible

        // warp's 4 labels, loaded once by lanes 0..3
        int myLab = 0;
        if (lane < RPW) myLab = labels[b * BATCH + wid * RPW + lane] & (C - 1);
        int c = __shfl_sync(FULL, myLab, k);      // this group's class

        const int j = wid * RPW + k;              // row slot in batch
        const int r = b * BATCH + j;

        // ---- emb row: lane's 4 float4s at (q + 8i) -> each LDG covers full 128B/row ----
        const float4* ev = reinterpret_cast<const float4*>(emb) + (size_t)r * 32 + q;
        float4 a0 = ev[0], a1 = ev[8], a2 = ev[16], a3 = ev[24];
        float ss = a0.x*a0.x + a0.y*a0.y + a0.z*a0.z + a0.w*a0.w
                 + a1.x*a1.x + a1.y*a1.y + a1.z*a1.z + a1.w*a1.w
                 + a2.x*a2.x + a2.y*a2.y + a2.z*a2.z + a2.w*a2.w
                 + a3.x*a3.x + a3.y*a3.y + a3.z*a3.z + a3.w*a3.w;
        ss += __shfl_xor_sync(FULL, ss, 1);
        ss += __shfl_xor_sync(FULL, ss, 2);
        ss += __shfl_xor_sync(FULL, ss, 4);       // group-wide row norm^2
        float s = rsqrtf(fmaxf(ss, 1e-24f));

        // ---- stage z ----
        float4* zs = reinterpret_cast<float4*>(&s_z[j][0]) + q;
        zs[0]  = make_float4(a0.x*s, a0.y*s, a0.z*s, a0.w*s);
        zs[8]  = make_float4(a1.x*s, a1.y*s, a1.z*s, a1.w*s);
        zs[16] = make_float4(a2.x*s, a2.y*s, a2.z*s, a2.w*s);
        zs[24] = make_float4(a3.x*s, a3.y*s, a3.z*s, a3.w*s);

        if (q == 0) atomicOr(&s_hit[c], 1ull << j);

        // ---- CE: lane's 8 logits at (q + 8i) ----
        const float4* lv = reinterpret_cast<const float4*>(logits) + (size_t)r * 16 + q;
        float4 x0 = lv[0], x1 = lv[8];
        float e = __expf(x0.x) + __expf(x0.y) + __expf(x0.z) + __expf(x0.w)
                + __expf(x1.x) + __expf(x1.y) + __expf(x1.z) + __expf(x1.w);
        e += __shfl_xor_sync(FULL, e, 1);
        e += __shfl_xor_sync(FULL, e, 2);
        e += __shfl_xor_sync(FULL, e, 4);
        float tv = __ldg(logits + (size_t)r * 64 + c);   // broadcast within group
        ce += logf(e) - tv;

        __syncthreads();

        // ---------- Phase B: iterate only hit rows via bitmask ----------
        #pragma unroll
        for (int cc = 0; cc < 4; cc++) {
            unsigned long long m = s_hit[wClass + cc];   // broadcast LDS.64
            cnt[cc] += __popcll(m);
            while (m) {
                int jj = __ffsll((long long)m) - 1;
                m &= m - 1;
                float4 z = *reinterpret_cast<const float4*>(&s_z[jj][lane * 4]);
                acc[cc].x += z.x; acc[cc].y += z.y; acc[cc].z += z.z; acc[cc].w += z.w;
            }
            s_hit[wClass + cc] = 0ull;            // reset own class (warp owns it)
        }
    }

    // ---------- Flush class sums + counts ----------
    float* part = g_buf + (blockIdx.x & (NPART - 1)) * (C * D);
    #pragma unroll
    for (int cc = 0; cc < 4; cc++) {
        red_v4(part + (wClass + cc) * D + lane * 4, acc[cc]);
        if (lane == 0 && cnt[cc] > 0)
            atomicAdd(&g_buf[CNT_OFF + wClass + cc], (float)cnt[cc]);
    }

    // ---------- Flush CE (each row was counted 8x) ----------
    #pragma unroll
    for (int o = 16; o; o >>= 1) ce += __shfl_xor_sync(FULL, ce, o);
    if (lane == 0) s_red[wid] = ce * 0.125f;
    __syncthreads();
    if (tid == 0) {
        float t = 0.0f;
        #pragma unroll
        for (int i = 0; i < NWARPS; i++) t += s_red[i];
        atomicAdd(&g_buf[CE_OFF], t);
    }

    // ---------- Last-block finalize ----------
    __threadfence();
    __syncthreads();
    if (tid == 0) {
        unsigned prev = atomicAdd((unsigned int*)&g_buf[DONE_OFF], 1u);
        s_last = (prev == gridDim.x - 1) ? 1 : 0;
    }
    __syncthreads();
    if (s_last) {
        __threadfence();
        float proto = 0.0f, nv = 0.0f;
        for (int c2 = wid; c2 < C; c2 += NWARPS) {
            float musq = 0.0f;
            #pragma unroll
            for (int kk = 0; kk < 4; kk++) {
                int d = lane + 32 * kk;
                float sum = 0.0f;
                #pragma unroll
                for (int p = 0; p < NPART; p++) sum += g_buf[p * (C * D) + c2 * D + d];
                musq += sum * sum;
            }
            #pragma unroll
            for (int o = 16; o; o >>= 1) musq += __shfl_xor_sync(FULL, musq, o);
            if (lane == 0) {
                float n = g_buf[CNT_OFF + c2];
                float sn = fmaxf(n, 1.0f);
                // sq == count (||z||^2 == 1): per_class = 1 - ||mu||^2
                float per = 1.0f - musq / (sn * sn);
                if (n > 1.0f) { proto += per; nv += 1.0f; }
            }
        }
        if (lane == 0) { s_red[wid] = proto; s_red2[wid] = nv; }
        __syncthreads();
        if (tid == 0) {
            float ps = 0.0f, ns = 0.0f;
            #pragma unroll
            for (int i = 0; i < NWARPS; i++) { ps += s_red[i]; ns += s_red2[i]; }
            float proto_loss = ps / fmaxf(ns, 1.0f);
            float cem = g_buf[CE_OFF] / (float)N;
            out[0] = 0.5f * cem + 0.5f * proto_loss;
        }
    }
}

extern "C" void kernel_launch(void* const* d_in, const int* in_sizes, int n_in,
                              void* d_out, int out_size) {
    const float* emb = (const float*)d_in[0];
    const float* logits = (const float*)d_in[1];
    const int* labels = (const int*)d_in[2];
    int N = in_sizes[0] / D;

    void* bufAddr = nullptr;
    cudaGetSymbolAddress(&bufAddr, g_buf);
    cudaMemsetAsync(bufAddr, 0, BUF_ELEMS * sizeof(float));

    main_kernel<<<GRID, 512>>>(emb, logits, labels, N, (float*)d_out);
}